// round 3
// baseline (speedup 1.0000x reference)
#include <cuda_runtime.h>
#include <math.h>

// Problem shape (fixed by the dataset)
#define S_TOT   258
#define C_DIM   64
#define H_DIM   64
#define W_DIM   64
#define NPIX    (C_DIM * H_DIM * W_DIM)     // 262144 pixels per layer
#define NPIX2   (NPIX / 2)                  // float2 per layer
#define NWIN    65536                       // C*32*32 output windows per layer

// output layout offsets (x_out, x_min, x_max, x_true_out concatenated)
#define OFF_XMIN   ((size_t)S_TOT * NWIN)
#define OFF_XMAX   (OFF_XMIN + NWIN)
#define OFF_XTRUE  (OFF_XMAX + NWIN)

// ---------------------------------------------------------------------------
// Fused kernel: one thread per 2x2 window.
//  - layer 0 pair loads give the centers
//  - layers 1..256 stream through an unroll-8 abs-sum loop; each unrolled
//    step also stores one zero eps output row, overlapping W with R traffic
//  - layer 257 (noise) is the remainder; its values stay in registers
//  - decision + scalar outputs at the end; exact path (statistically dead
//    for this input: |l*-u_other| ~ 400 sigma) does a rare gather rewrite
// ---------------------------------------------------------------------------
__global__ void __launch_bounds__(128) k_fused(const float* __restrict__ x,
                                               const float* __restrict__ xtrue,
                                               float* __restrict__ out) {
    const int win = blockIdx.x * 128 + threadIdx.x;     // 0..65535
    const int c  = win >> 10;
    const int ho = (win >> 5) & 31;
    const int wo = win & 31;
    const int h0 = 2 * ho;

    // float2 indices of the window's top/bottom 2-element segments
    const int r0 = (c * H_DIM + h0) * (W_DIM / 2) + wo;
    const int r1 = r0 + (W_DIM / 2);

    const float2* __restrict__ x2 = (const float2*)x;

    // layer 0: centers
    const float2 t0 = x2[r0];
    const float2 b0 = x2[r1];

    // eps_abs accumulation over layers 1..257, zero-row stores interleaved
    float etx = 0.f, ety = 0.f, ebx = 0.f, eby = 0.f;
    const float2* __restrict__ xs = x2 + NPIX2;         // layer 1
    float* __restrict__ zs = out + (size_t)NWIN + win;  // eps row s=1

    #pragma unroll 1
    for (int s0 = 0; s0 < 256; s0 += 8) {
        float2 a0 = xs[(size_t)(s0 + 0) * NPIX2 + r0];
        float2 b_0 = xs[(size_t)(s0 + 0) * NPIX2 + r1];
        float2 a1 = xs[(size_t)(s0 + 1) * NPIX2 + r0];
        float2 b_1 = xs[(size_t)(s0 + 1) * NPIX2 + r1];
        float2 a2 = xs[(size_t)(s0 + 2) * NPIX2 + r0];
        float2 b_2 = xs[(size_t)(s0 + 2) * NPIX2 + r1];
        float2 a3 = xs[(size_t)(s0 + 3) * NPIX2 + r0];
        float2 b_3 = xs[(size_t)(s0 + 3) * NPIX2 + r1];
        float2 a4 = xs[(size_t)(s0 + 4) * NPIX2 + r0];
        float2 b_4 = xs[(size_t)(s0 + 4) * NPIX2 + r1];
        float2 a5 = xs[(size_t)(s0 + 5) * NPIX2 + r0];
        float2 b_5 = xs[(size_t)(s0 + 5) * NPIX2 + r1];
        float2 a6 = xs[(size_t)(s0 + 6) * NPIX2 + r0];
        float2 b_6 = xs[(size_t)(s0 + 6) * NPIX2 + r1];
        float2 a7 = xs[(size_t)(s0 + 7) * NPIX2 + r0];
        float2 b_7 = xs[(size_t)(s0 + 7) * NPIX2 + r1];

        etx += fabsf(a0.x); ety += fabsf(a0.y); ebx += fabsf(b_0.x); eby += fabsf(b_0.y);
        etx += fabsf(a1.x); ety += fabsf(a1.y); ebx += fabsf(b_1.x); eby += fabsf(b_1.y);
        etx += fabsf(a2.x); ety += fabsf(a2.y); ebx += fabsf(b_2.x); eby += fabsf(b_2.y);
        etx += fabsf(a3.x); ety += fabsf(a3.y); ebx += fabsf(b_3.x); eby += fabsf(b_3.y);
        etx += fabsf(a4.x); ety += fabsf(a4.y); ebx += fabsf(b_4.x); eby += fabsf(b_4.y);
        etx += fabsf(a5.x); ety += fabsf(a5.y); ebx += fabsf(b_5.x); eby += fabsf(b_5.y);
        etx += fabsf(a6.x); ety += fabsf(a6.y); ebx += fabsf(b_6.x); eby += fabsf(b_6.y);
        etx += fabsf(a7.x); ety += fabsf(a7.y); ebx += fabsf(b_7.x); eby += fabsf(b_7.y);

        // zero eps rows s0+1 .. s0+8 (out rows 1..256), overlapped with loads
        zs[(size_t)(s0 + 0) * NWIN] = 0.f;
        zs[(size_t)(s0 + 1) * NWIN] = 0.f;
        zs[(size_t)(s0 + 2) * NWIN] = 0.f;
        zs[(size_t)(s0 + 3) * NWIN] = 0.f;
        zs[(size_t)(s0 + 4) * NWIN] = 0.f;
        zs[(size_t)(s0 + 5) * NWIN] = 0.f;
        zs[(size_t)(s0 + 6) * NWIN] = 0.f;
        zs[(size_t)(s0 + 7) * NWIN] = 0.f;
    }

    // layer 257 (noise) — keep values in registers for the exact path
    const float2 an = xs[(size_t)256 * NPIX2 + r0];
    const float2 bn = xs[(size_t)256 * NPIX2 + r1];
    etx += fabsf(an.x); ety += fabsf(an.y); ebx += fabsf(bn.x); eby += fabsf(bn.y);

    // interval bounds for the 4 window elements (K order: [t.x, t.y, b.x, b.y])
    const float lo0 = t0.x - etx, lo1 = t0.y - ety, lo2 = b0.x - ebx, lo3 = b0.y - eby;
    const float hi0 = t0.x + etx, hi1 = t0.y + ety, hi2 = b0.x + ebx, hi3 = b0.y + eby;

    // argmax of lower bounds, first occurrence wins (matches jnp.argmax)
    int   istar = 0;
    float lbest = lo0;
    if (lo1 > lbest) { lbest = lo1; istar = 1; }
    if (lo2 > lbest) { lbest = lo2; istar = 2; }
    if (lo3 > lbest) { lbest = lo3; istar = 3; }

    const float umax = fmaxf(fmaxf(hi0, hi1), fmaxf(hi2, hi3));

    float uo = -3.0e38f;
    if (istar != 0) uo = fmaxf(uo, hi0);
    if (istar != 1) uo = fmaxf(uo, hi1);
    if (istar != 2) uo = fmaxf(uo, hi2);
    if (istar != 3) uo = fmaxf(uo, hi3);

    const bool exact = (lbest >= uo);

    float center, noise, xmn, xmx;
    if (exact) {
        const float x0g  = (istar == 0) ? t0.x : (istar == 1) ? t0.y
                         : (istar == 2) ? b0.x : b0.y;
        const float epsg = (istar == 0) ? etx  : (istar == 1) ? ety
                         : (istar == 2) ? ebx  : eby;
        const float ng   = (istar == 0) ? an.x : (istar == 1) ? an.y
                         : (istar == 2) ? bn.x : bn.y;
        center = x0g;
        noise  = fabsf(ng);
        xmn = center - epsg;          // = l_star
        xmx = center + epsg;          // = u[i_star]

        // rare: rewrite the eps rows with the gathered affine form
        const int dy = istar >> 1;
        const int dx = istar & 1;
        const size_t poff = ((size_t)c * H_DIM + (h0 + dy)) * W_DIM + (2 * wo + dx);
        const float* xg = x + NPIX + poff;            // x[1] at chosen pixel
        float* o = out + (size_t)NWIN + win;
        for (int s = 0; s < S_TOT - 2; s++) {
            o[(size_t)s * NWIN] = xg[(size_t)s * NPIX];
        }
    } else {
        center = 0.5f * (lbest + umax);
        noise  = 0.5f * (umax - lbest);
        xmn = center - noise;
        xmx = center + noise;
    }

    // scalar outputs
    out[win]                              = center;   // s = 0
    out[(size_t)(S_TOT - 1) * NWIN + win] = noise;    // s = 257
    out[OFF_XMIN + win]  = xmn;
    out[OFF_XMAX + win]  = xmx;

    // x_true max-pool
    const float2* __restrict__ xt2 = (const float2*)xtrue;
    const float2 tt = xt2[r0];
    const float2 tb = xt2[r1];
    out[OFF_XTRUE + win] = fmaxf(fmaxf(tt.x, tt.y), fmaxf(tb.x, tb.y));
}

extern "C" void kernel_launch(void* const* d_in, const int* in_sizes, int n_in,
                              void* d_out, int out_size) {
    const float* x  = (const float*)d_in[0];
    const float* xt = (const float*)d_in[1];
    float* out = (float*)d_out;
    (void)in_sizes; (void)n_in; (void)out_size;

    k_fused<<<NWIN / 128, 128>>>(x, xt, out);
}

// round 6
// speedup vs baseline: 1.5210x; 1.5210x over previous
#include <cuda_runtime.h>
#include <math.h>

// Problem shape (fixed by the dataset)
#define S_TOT   258
#define C_DIM   64
#define H_DIM   64
#define W_DIM   64
#define NPIX    (C_DIM * H_DIM * W_DIM)     // 262144 pixels per layer
#define NPIX2   (NPIX / 2)                  // float2 per layer
#define NWIN    65536                       // output windows per layer

// output layout offsets (x_out, x_min, x_max, x_true_out concatenated)
#define OFF_XMIN   ((size_t)S_TOT * NWIN)
#define OFF_XMAX   (OFF_XMIN + NWIN)
#define OFF_XTRUE  (OFF_XMAX + NWIN)

// ---------------------------------------------------------------------------
// Fused kernel, high-parallelism variant.
// Block = 256 threads = 32 windows (w = tid&31) x 8 S-chunks (ch = tid>>5).
// Each thread abs-accumulates 32 symbol layers for its window's 4 pixels and
// zeroes the matching 32 eps output rows (stores overlap loads). Chunks are
// reduced via smem; the first warp does the decision + scalar outputs and the
// (statistically dead) exact-path rewrite.
// ---------------------------------------------------------------------------
__global__ void __launch_bounds__(256) k_fused(const float* __restrict__ x,
                                               const float* __restrict__ xtrue,
                                               float* __restrict__ out) {
    __shared__ float4 sm[8][32];

    const int t  = threadIdx.x;
    const int w  = t & 31;
    const int ch = t >> 5;
    const int win = blockIdx.x * 32 + w;    // 32 consecutive windows per block
    const int c  = win >> 10;
    const int ho = (win >> 5) & 31;
    const int h0 = 2 * ho;

    // float2 indices of the window's top/bottom 2-element segments
    const int r0 = (c * H_DIM + h0) * (W_DIM / 2) + w;   // wo == w (win_base % 32 == 0)
    const int r1 = r0 + (W_DIM / 2);

    const float2* __restrict__ x2 = (const float2*)x;

    // this thread's 32 symbol layers: s = 1 + ch*32 .. 32 + ch*32
    const float2* __restrict__ p = x2 + (size_t)(1 + ch * 32) * NPIX2;
    float* __restrict__ zp = out + (size_t)(1 + ch * 32) * NWIN + win;

    float etx = 0.f, ety = 0.f, ebx = 0.f, eby = 0.f;

    #pragma unroll 1
    for (int i = 0; i < 32; i += 8) {
        float2 a0 = p[(size_t)(i + 0) * NPIX2 + r0];
        float2 b0 = p[(size_t)(i + 0) * NPIX2 + r1];
        float2 a1 = p[(size_t)(i + 1) * NPIX2 + r0];
        float2 b1 = p[(size_t)(i + 1) * NPIX2 + r1];
        float2 a2 = p[(size_t)(i + 2) * NPIX2 + r0];
        float2 b2 = p[(size_t)(i + 2) * NPIX2 + r1];
        float2 a3 = p[(size_t)(i + 3) * NPIX2 + r0];
        float2 b3 = p[(size_t)(i + 3) * NPIX2 + r1];
        float2 a4 = p[(size_t)(i + 4) * NPIX2 + r0];
        float2 b4 = p[(size_t)(i + 4) * NPIX2 + r1];
        float2 a5 = p[(size_t)(i + 5) * NPIX2 + r0];
        float2 b5 = p[(size_t)(i + 5) * NPIX2 + r1];
        float2 a6 = p[(size_t)(i + 6) * NPIX2 + r0];
        float2 b6 = p[(size_t)(i + 6) * NPIX2 + r1];
        float2 a7 = p[(size_t)(i + 7) * NPIX2 + r0];
        float2 b7 = p[(size_t)(i + 7) * NPIX2 + r1];

        etx += fabsf(a0.x); ety += fabsf(a0.y); ebx += fabsf(b0.x); eby += fabsf(b0.y);
        etx += fabsf(a1.x); ety += fabsf(a1.y); ebx += fabsf(b1.x); eby += fabsf(b1.y);
        etx += fabsf(a2.x); ety += fabsf(a2.y); ebx += fabsf(b2.x); eby += fabsf(b2.y);
        etx += fabsf(a3.x); ety += fabsf(a3.y); ebx += fabsf(b3.x); eby += fabsf(b3.y);
        etx += fabsf(a4.x); ety += fabsf(a4.y); ebx += fabsf(b4.x); eby += fabsf(b4.y);
        etx += fabsf(a5.x); ety += fabsf(a5.y); ebx += fabsf(b5.x); eby += fabsf(b5.y);
        etx += fabsf(a6.x); ety += fabsf(a6.y); ebx += fabsf(b6.x); eby += fabsf(b6.y);
        etx += fabsf(a7.x); ety += fabsf(a7.y); ebx += fabsf(b7.x); eby += fabsf(b7.y);

        // zero the 8 matching eps output rows (overlap W with R)
        zp[(size_t)(i + 0) * NWIN] = 0.f;
        zp[(size_t)(i + 1) * NWIN] = 0.f;
        zp[(size_t)(i + 2) * NWIN] = 0.f;
        zp[(size_t)(i + 3) * NWIN] = 0.f;
        zp[(size_t)(i + 4) * NWIN] = 0.f;
        zp[(size_t)(i + 5) * NWIN] = 0.f;
        zp[(size_t)(i + 6) * NWIN] = 0.f;
        zp[(size_t)(i + 7) * NWIN] = 0.f;
    }

    sm[ch][w] = make_float4(etx, ety, ebx, eby);
    __syncthreads();

    // ---- first warp: reduce chunks, decide, write scalar outputs ----
    if (t < 32) {
        float4 s0 = sm[0][w], s1 = sm[1][w], s2 = sm[2][w], s3 = sm[3][w];
        float4 s4 = sm[4][w], s5 = sm[5][w], s6 = sm[6][w], s7 = sm[7][w];
        float ET = s0.x + s1.x + s2.x + s3.x + s4.x + s5.x + s6.x + s7.x;
        float EY = s0.y + s1.y + s2.y + s3.y + s4.y + s5.y + s6.y + s7.y;
        float EB = s0.z + s1.z + s2.z + s3.z + s4.z + s5.z + s6.z + s7.z;
        float EW = s0.w + s1.w + s2.w + s3.w + s4.w + s5.w + s6.w + s7.w;

        // layer 0 centers + layer 257 (noise) values
        const float2 t0 = x2[r0];
        const float2 b0 = x2[r1];
        const float2 an = x2[(size_t)(S_TOT - 1) * NPIX2 + r0];
        const float2 bn = x2[(size_t)(S_TOT - 1) * NPIX2 + r1];
        ET += fabsf(an.x); EY += fabsf(an.y); EB += fabsf(bn.x); EW += fabsf(bn.y);

        // interval bounds (K order: [t.x, t.y, b.x, b.y])
        const float lo0 = t0.x - ET, lo1 = t0.y - EY, lo2 = b0.x - EB, lo3 = b0.y - EW;
        const float hi0 = t0.x + ET, hi1 = t0.y + EY, hi2 = b0.x + EB, hi3 = b0.y + EW;

        // argmax of lower bounds, first occurrence wins (matches jnp.argmax)
        int   istar = 0;
        float lbest = lo0;
        if (lo1 > lbest) { lbest = lo1; istar = 1; }
        if (lo2 > lbest) { lbest = lo2; istar = 2; }
        if (lo3 > lbest) { lbest = lo3; istar = 3; }

        const float umax = fmaxf(fmaxf(hi0, hi1), fmaxf(hi2, hi3));

        float uo = -3.0e38f;
        if (istar != 0) uo = fmaxf(uo, hi0);
        if (istar != 1) uo = fmaxf(uo, hi1);
        if (istar != 2) uo = fmaxf(uo, hi2);
        if (istar != 3) uo = fmaxf(uo, hi3);

        const bool exact = (lbest >= uo);

        float center, noise, xmn, xmx;
        if (exact) {
            const float x0g  = (istar == 0) ? t0.x : (istar == 1) ? t0.y
                             : (istar == 2) ? b0.x : b0.y;
            const float epsg = (istar == 0) ? ET   : (istar == 1) ? EY
                             : (istar == 2) ? EB   : EW;
            const float ng   = (istar == 0) ? an.x : (istar == 1) ? an.y
                             : (istar == 2) ? bn.x : bn.y;
            center = x0g;
            noise  = fabsf(ng);
            xmn = center - epsg;          // = l_star
            xmx = center + epsg;          // = u[i_star]

            // rare: rewrite the eps rows with the gathered affine form.
            // Ordered after the zero stores by the __syncthreads above.
            const int dy = istar >> 1;
            const int dx = istar & 1;
            const size_t poff = ((size_t)c * H_DIM + (h0 + dy)) * W_DIM + (2 * w + dx);
            const float* xg = x + NPIX + poff;        // x[1] at chosen pixel
            float* o = out + (size_t)NWIN + win;
            for (int s = 0; s < S_TOT - 2; s++) {
                o[(size_t)s * NWIN] = xg[(size_t)s * NPIX];
            }
        } else {
            center = 0.5f * (lbest + umax);
            noise  = 0.5f * (umax - lbest);
            xmn = center - noise;
            xmx = center + noise;
        }

        // scalar outputs
        out[win]                              = center;   // s = 0
        out[(size_t)(S_TOT - 1) * NWIN + win] = noise;    // s = 257
        out[OFF_XMIN + win]  = xmn;
        out[OFF_XMAX + win]  = xmx;

        // x_true max-pool
        const float2* __restrict__ xt2 = (const float2*)xtrue;
        const float2 tt = xt2[r0];
        const float2 tb = xt2[r1];
        out[OFF_XTRUE + win] = fmaxf(fmaxf(tt.x, tt.y), fmaxf(tb.x, tb.y));
    }
}

extern "C" void kernel_launch(void* const* d_in, const int* in_sizes, int n_in,
                              void* d_out, int out_size) {
    const float* x  = (const float*)d_in[0];
    const float* xt = (const float*)d_in[1];
    float* out = (float*)d_out;
    (void)in_sizes; (void)n_in; (void)out_size;

    k_fused<<<NWIN / 32, 256>>>(x, xt, out);
}

// round 7
// speedup vs baseline: 1.5933x; 1.0475x over previous
#include <cuda_runtime.h>
#include <math.h>

// Problem shape (fixed by the dataset)
#define S_TOT   258
#define C_DIM   64
#define H_DIM   64
#define W_DIM   64
#define NPIX    (C_DIM * H_DIM * W_DIM)     // 262144 pixels per layer
#define NPIX2   (NPIX / 2)                  // float2 per layer
#define NPIX4   (NPIX / 4)                  // float4 per layer
#define NWIN    65536                       // output windows per layer

// output layout offsets (x_out, x_min, x_max, x_true_out concatenated)
#define OFF_XMIN   ((size_t)S_TOT * NWIN)
#define OFF_XMAX   (OFF_XMIN + NWIN)
#define OFF_XTRUE  (OFF_XMAX + NWIN)

// ---------------------------------------------------------------------------
// Fused kernel, float4-strip variant.
// A block's 32 windows share (c, ho): their pixels form ONE contiguous
// 128-float strip per layer (row h0 then row h0+1). Block = 256 threads =
// 8 S-chunks x 32 lanes; lane w of chunk ch loads strip-float4 #w for its 32
// layers (one LDG.128 per layer) and abs-accumulates into a float4. The smem
// reduction reassociates pixels to windows: epilogue lane w reads float4s
// (w>>1) [top row] and 16+(w>>1) [bottom row], picking .xy / .zw by (w&1).
// Zero eps-row stores stay interleaved with the loads; the statistically
// dead exact path rewrites after __syncthreads.
// ---------------------------------------------------------------------------
__global__ void __launch_bounds__(256, 8) k_fused(const float* __restrict__ x,
                                                  const float* __restrict__ xtrue,
                                                  float* __restrict__ out) {
    __shared__ float4 sm[8][32];

    const int t  = threadIdx.x;
    const int w  = t & 31;
    const int ch = t >> 5;
    const int wb  = blockIdx.x * 32;        // first window of this block
    const int win = wb + w;
    const int c  = win >> 10;
    const int ho = (win >> 5) & 31;
    const int h0 = 2 * ho;

    // base of the block's 128-float strip, in float4 units (shared by block:
    // wb has wo=0, so c/ho derived from win==wb+w give the same c,ho for all w
    // only when reading strip; compute from wb to be explicit)
    const int cb  = wb >> 10;
    const int hob = (wb >> 5) & 31;
    const int fb  = (cb * H_DIM + 2 * hob) * (W_DIM / 4);   // float4 index

    const float4* __restrict__ x4 = (const float4*)x;
    const float2* __restrict__ x2 = (const float2*)x;

    // this chunk's 32 symbol layers: s = 1 + ch*32 .. 32 + ch*32
    const float4* __restrict__ p = x4 + (size_t)(1 + ch * 32) * NPIX4 + fb + w;
    float* __restrict__ zp = out + (size_t)(1 + ch * 32) * NWIN + win;

    float ax = 0.f, ay = 0.f, az = 0.f, aw = 0.f;

    #pragma unroll 1
    for (int i = 0; i < 32; i += 4) {
        float4 v0 = p[(size_t)(i + 0) * NPIX4];
        float4 v1 = p[(size_t)(i + 1) * NPIX4];
        float4 v2 = p[(size_t)(i + 2) * NPIX4];
        float4 v3 = p[(size_t)(i + 3) * NPIX4];

        ax += fabsf(v0.x); ay += fabsf(v0.y); az += fabsf(v0.z); aw += fabsf(v0.w);
        ax += fabsf(v1.x); ay += fabsf(v1.y); az += fabsf(v1.z); aw += fabsf(v1.w);
        ax += fabsf(v2.x); ay += fabsf(v2.y); az += fabsf(v2.z); aw += fabsf(v2.w);
        ax += fabsf(v3.x); ay += fabsf(v3.y); az += fabsf(v3.z); aw += fabsf(v3.w);

        // zero the 4 matching eps output rows (overlap W with R)
        zp[(size_t)(i + 0) * NWIN] = 0.f;
        zp[(size_t)(i + 1) * NWIN] = 0.f;
        zp[(size_t)(i + 2) * NWIN] = 0.f;
        zp[(size_t)(i + 3) * NWIN] = 0.f;
    }

    sm[ch][w] = make_float4(ax, ay, az, aw);
    __syncthreads();

    // ---- first warp: reduce chunks, reassociate pixels->window, decide ----
    if (t < 32) {
        const int lt = w >> 1;          // top-row float4 lane for this window
        const int lb = 16 + lt;         // bottom-row float4 lane

        float4 T = make_float4(0.f, 0.f, 0.f, 0.f);
        float4 B = make_float4(0.f, 0.f, 0.f, 0.f);
        #pragma unroll
        for (int k = 0; k < 8; k++) {
            float4 a = sm[k][lt];
            float4 b = sm[k][lb];
            T.x += a.x; T.y += a.y; T.z += a.z; T.w += a.w;
            B.x += b.x; B.y += b.y; B.z += b.z; B.w += b.w;
        }
        // select this window's pixel pair within the float4
        const bool odd = (w & 1);
        float ET = odd ? T.z : T.x;     // eps_abs of top-left pixel
        float EY = odd ? T.w : T.y;     // top-right
        float EB = odd ? B.z : B.x;     // bottom-left
        float EW = odd ? B.w : B.y;     // bottom-right

        // float2 indices of the window's top/bottom segments
        const int r0 = (c * H_DIM + h0) * (W_DIM / 2) + w;
        const int r1 = r0 + (W_DIM / 2);

        // layer 0 centers + layer 257 (noise) values
        const float2 t0 = x2[r0];
        const float2 b0 = x2[r1];
        const float2 an = x2[(size_t)(S_TOT - 1) * NPIX2 + r0];
        const float2 bn = x2[(size_t)(S_TOT - 1) * NPIX2 + r1];
        ET += fabsf(an.x); EY += fabsf(an.y); EB += fabsf(bn.x); EW += fabsf(bn.y);

        // interval bounds (K order: [t.x, t.y, b.x, b.y])
        const float lo0 = t0.x - ET, lo1 = t0.y - EY, lo2 = b0.x - EB, lo3 = b0.y - EW;
        const float hi0 = t0.x + ET, hi1 = t0.y + EY, hi2 = b0.x + EB, hi3 = b0.y + EW;

        // argmax of lower bounds, first occurrence wins (matches jnp.argmax)
        int   istar = 0;
        float lbest = lo0;
        if (lo1 > lbest) { lbest = lo1; istar = 1; }
        if (lo2 > lbest) { lbest = lo2; istar = 2; }
        if (lo3 > lbest) { lbest = lo3; istar = 3; }

        const float umax = fmaxf(fmaxf(hi0, hi1), fmaxf(hi2, hi3));

        float uo = -3.0e38f;
        if (istar != 0) uo = fmaxf(uo, hi0);
        if (istar != 1) uo = fmaxf(uo, hi1);
        if (istar != 2) uo = fmaxf(uo, hi2);
        if (istar != 3) uo = fmaxf(uo, hi3);

        const bool exact = (lbest >= uo);

        float center, noise, xmn, xmx;
        if (exact) {
            const float x0g  = (istar == 0) ? t0.x : (istar == 1) ? t0.y
                             : (istar == 2) ? b0.x : b0.y;
            const float epsg = (istar == 0) ? ET   : (istar == 1) ? EY
                             : (istar == 2) ? EB   : EW;
            const float ng   = (istar == 0) ? an.x : (istar == 1) ? an.y
                             : (istar == 2) ? bn.x : bn.y;
            center = x0g;
            noise  = fabsf(ng);
            xmn = center - epsg;          // = l_star
            xmx = center + epsg;          // = u[i_star]

            // rare: rewrite the eps rows with the gathered affine form.
            // Ordered after the zero stores by the __syncthreads above.
            const int dy = istar >> 1;
            const int dx = istar & 1;
            const size_t poff = ((size_t)c * H_DIM + (h0 + dy)) * W_DIM + (2 * w + dx);
            const float* xg = x + NPIX + poff;        // x[1] at chosen pixel
            float* o = out + (size_t)NWIN + win;
            for (int s = 0; s < S_TOT - 2; s++) {
                o[(size_t)s * NWIN] = xg[(size_t)s * NPIX];
            }
        } else {
            center = 0.5f * (lbest + umax);
            noise  = 0.5f * (umax - lbest);
            xmn = center - noise;
            xmx = center + noise;
        }

        // scalar outputs
        out[win]                              = center;   // s = 0
        out[(size_t)(S_TOT - 1) * NWIN + win] = noise;    // s = 257
        out[OFF_XMIN + win]  = xmn;
        out[OFF_XMAX + win]  = xmx;

        // x_true max-pool
        const float2* __restrict__ xt2 = (const float2*)xtrue;
        const float2 tt = xt2[r0];
        const float2 tb = xt2[r1];
        out[OFF_XTRUE + win] = fmaxf(fmaxf(tt.x, tt.y), fmaxf(tb.x, tb.y));
    }
}

extern "C" void kernel_launch(void* const* d_in, const int* in_sizes, int n_in,
                              void* d_out, int out_size) {
    const float* x  = (const float*)d_in[0];
    const float* xt = (const float*)d_in[1];
    float* out = (float*)d_out;
    (void)in_sizes; (void)n_in; (void)out_size;

    k_fused<<<NWIN / 32, 256>>>(x, xt, out);
}

// round 8
// speedup vs baseline: 1.6301x; 1.0231x over previous
#include <cuda_runtime.h>
#include <math.h>

// Problem shape (fixed by the dataset)
#define S_TOT   258
#define C_DIM   64
#define H_DIM   64
#define W_DIM   64
#define NPIX    (C_DIM * H_DIM * W_DIM)     // 262144 pixels per layer
#define NPIX2   (NPIX / 2)                  // float2 per layer
#define NPIX4   (NPIX / 4)                  // float4 per layer
#define NWIN    65536                       // output windows per layer

// output layout offsets (x_out, x_min, x_max, x_true_out concatenated)
#define OFF_XMIN   ((size_t)S_TOT * NWIN)
#define OFF_XMAX   (OFF_XMIN + NWIN)
#define OFF_XTRUE  (OFF_XMAX + NWIN)

// ---------------------------------------------------------------------------
// Fused kernel, single-wave variant.
// One block per strip (the 128 contiguous floats feeding 32 windows that
// share (c, ho)). Block = 128 threads = 4 S-chunks (64 layers each) x 32
// lanes; lane w loads strip-float4 #w per layer (LDG.128, streaming) and
// abs-accumulates. Zero eps-row stores (streaming) are interleaved with the
// loads. 16 blocks/SM resident -> all 2048 blocks fit in ONE wave (no tail).
// smem reduce + first-warp decision epilogue; statistically dead exact path
// rewrites after __syncthreads.
// ---------------------------------------------------------------------------
__global__ void __launch_bounds__(128, 16) k_fused(const float* __restrict__ x,
                                                   const float* __restrict__ xtrue,
                                                   float* __restrict__ out) {
    __shared__ float4 sm[4][32];

    const int t  = threadIdx.x;
    const int w  = t & 31;
    const int ch = t >> 5;                  // 0..3, 64 layers each
    const int wb  = blockIdx.x * 32;        // first window of this block
    const int win = wb + w;
    const int c  = win >> 10;
    const int ho = (win >> 5) & 31;
    const int h0 = 2 * ho;

    // base of the block's 128-float strip, in float4 units
    const int cb  = wb >> 10;
    const int hob = (wb >> 5) & 31;
    const int fb  = (cb * H_DIM + 2 * hob) * (W_DIM / 4);   // float4 index

    const float4* __restrict__ x4 = (const float4*)x;
    const float2* __restrict__ x2 = (const float2*)x;

    // this chunk's 64 symbol layers: s = 1 + ch*64 .. 64 + ch*64
    const float4* __restrict__ p = x4 + (size_t)(1 + ch * 64) * NPIX4 + fb + w;
    float* __restrict__ zp = out + (size_t)(1 + ch * 64) * NWIN + win;

    float ax = 0.f, ay = 0.f, az = 0.f, aw = 0.f;

    #pragma unroll 1
    for (int i = 0; i < 64; i += 4) {
        float4 v0 = __ldcs(p + (size_t)(i + 0) * NPIX4);
        float4 v1 = __ldcs(p + (size_t)(i + 1) * NPIX4);
        float4 v2 = __ldcs(p + (size_t)(i + 2) * NPIX4);
        float4 v3 = __ldcs(p + (size_t)(i + 3) * NPIX4);

        ax += fabsf(v0.x); ay += fabsf(v0.y); az += fabsf(v0.z); aw += fabsf(v0.w);
        ax += fabsf(v1.x); ay += fabsf(v1.y); az += fabsf(v1.z); aw += fabsf(v1.w);
        ax += fabsf(v2.x); ay += fabsf(v2.y); az += fabsf(v2.z); aw += fabsf(v2.w);
        ax += fabsf(v3.x); ay += fabsf(v3.y); az += fabsf(v3.z); aw += fabsf(v3.w);

        // zero the 4 matching eps output rows (streaming, overlap W with R)
        __stcs(zp + (size_t)(i + 0) * NWIN, 0.f);
        __stcs(zp + (size_t)(i + 1) * NWIN, 0.f);
        __stcs(zp + (size_t)(i + 2) * NWIN, 0.f);
        __stcs(zp + (size_t)(i + 3) * NWIN, 0.f);
    }

    sm[ch][w] = make_float4(ax, ay, az, aw);
    __syncthreads();

    // ---- first warp: reduce chunks, reassociate pixels->window, decide ----
    if (t < 32) {
        const int lt = w >> 1;          // top-row float4 lane for this window
        const int lb = 16 + lt;         // bottom-row float4 lane

        float4 T = make_float4(0.f, 0.f, 0.f, 0.f);
        float4 B = make_float4(0.f, 0.f, 0.f, 0.f);
        #pragma unroll
        for (int k = 0; k < 4; k++) {
            float4 a = sm[k][lt];
            float4 b = sm[k][lb];
            T.x += a.x; T.y += a.y; T.z += a.z; T.w += a.w;
            B.x += b.x; B.y += b.y; B.z += b.z; B.w += b.w;
        }
        // select this window's pixel pair within the float4
        const bool odd = (w & 1);
        float ET = odd ? T.z : T.x;     // eps_abs of top-left pixel
        float EY = odd ? T.w : T.y;     // top-right
        float EB = odd ? B.z : B.x;     // bottom-left
        float EW = odd ? B.w : B.y;     // bottom-right

        // float2 indices of the window's top/bottom segments
        const int r0 = (c * H_DIM + h0) * (W_DIM / 2) + w;
        const int r1 = r0 + (W_DIM / 2);

        // layer 0 centers + layer 257 (noise) values
        const float2 t0 = x2[r0];
        const float2 b0 = x2[r1];
        const float2 an = x2[(size_t)(S_TOT - 1) * NPIX2 + r0];
        const float2 bn = x2[(size_t)(S_TOT - 1) * NPIX2 + r1];
        ET += fabsf(an.x); EY += fabsf(an.y); EB += fabsf(bn.x); EW += fabsf(bn.y);

        // interval bounds (K order: [t.x, t.y, b.x, b.y])
        const float lo0 = t0.x - ET, lo1 = t0.y - EY, lo2 = b0.x - EB, lo3 = b0.y - EW;
        const float hi0 = t0.x + ET, hi1 = t0.y + EY, hi2 = b0.x + EB, hi3 = b0.y + EW;

        // argmax of lower bounds, first occurrence wins (matches jnp.argmax)
        int   istar = 0;
        float lbest = lo0;
        if (lo1 > lbest) { lbest = lo1; istar = 1; }
        if (lo2 > lbest) { lbest = lo2; istar = 2; }
        if (lo3 > lbest) { lbest = lo3; istar = 3; }

        const float umax = fmaxf(fmaxf(hi0, hi1), fmaxf(hi2, hi3));

        float uo = -3.0e38f;
        if (istar != 0) uo = fmaxf(uo, hi0);
        if (istar != 1) uo = fmaxf(uo, hi1);
        if (istar != 2) uo = fmaxf(uo, hi2);
        if (istar != 3) uo = fmaxf(uo, hi3);

        const bool exact = (lbest >= uo);

        float center, noise, xmn, xmx;
        if (exact) {
            const float x0g  = (istar == 0) ? t0.x : (istar == 1) ? t0.y
                             : (istar == 2) ? b0.x : b0.y;
            const float epsg = (istar == 0) ? ET   : (istar == 1) ? EY
                             : (istar == 2) ? EB   : EW;
            const float ng   = (istar == 0) ? an.x : (istar == 1) ? an.y
                             : (istar == 2) ? bn.x : bn.y;
            center = x0g;
            noise  = fabsf(ng);
            xmn = center - epsg;          // = l_star
            xmx = center + epsg;          // = u[i_star]

            // rare: rewrite the eps rows with the gathered affine form.
            // Ordered after the zero stores by the __syncthreads above.
            const int dy = istar >> 1;
            const int dx = istar & 1;
            const size_t poff = ((size_t)c * H_DIM + (h0 + dy)) * W_DIM + (2 * w + dx);
            const float* xg = x + NPIX + poff;        // x[1] at chosen pixel
            float* o = out + (size_t)NWIN + win;
            for (int s = 0; s < S_TOT - 2; s++) {
                o[(size_t)s * NWIN] = xg[(size_t)s * NPIX];
            }
        } else {
            center = 0.5f * (lbest + umax);
            noise  = 0.5f * (umax - lbest);
            xmn = center - noise;
            xmx = center + noise;
        }

        // scalar outputs
        out[win]                              = center;   // s = 0
        out[(size_t)(S_TOT - 1) * NWIN + win] = noise;    // s = 257
        out[OFF_XMIN + win]  = xmn;
        out[OFF_XMAX + win]  = xmx;

        // x_true max-pool
        const float2* __restrict__ xt2 = (const float2*)xtrue;
        const float2 tt = xt2[r0];
        const float2 tb = xt2[r1];
        out[OFF_XTRUE + win] = fmaxf(fmaxf(tt.x, tt.y), fmaxf(tb.x, tb.y));
    }
}

extern "C" void kernel_launch(void* const* d_in, const int* in_sizes, int n_in,
                              void* d_out, int out_size) {
    const float* x  = (const float*)d_in[0];
    const float* xt = (const float*)d_in[1];
    float* out = (float*)d_out;
    (void)in_sizes; (void)n_in; (void)out_size;

    k_fused<<<NWIN / 32, 128>>>(x, xt, out);
}

// round 9
// speedup vs baseline: 1.6379x; 1.0048x over previous
#include <cuda_runtime.h>
#include <math.h>

// Problem shape (fixed by the dataset)
#define S_TOT   258
#define C_DIM   64
#define H_DIM   64
#define W_DIM   64
#define NPIX    (C_DIM * H_DIM * W_DIM)     // 262144 pixels per layer
#define NPIX2   (NPIX / 2)                  // float2 per layer
#define NPIX4   (NPIX / 4)                  // float4 per layer
#define NWIN    65536                       // output windows per layer

// output layout offsets (x_out, x_min, x_max, x_true_out concatenated)
#define OFF_XMIN   ((size_t)S_TOT * NWIN)
#define OFF_XMAX   (OFF_XMIN + NWIN)
#define OFF_XTRUE  (OFF_XMAX + NWIN)

// ---------------------------------------------------------------------------
// Fused kernel, single-wave + prefetch variant.
// One block per strip (128 contiguous floats feeding 32 windows sharing
// (c, ho)). Block = 128 threads = 4 S-chunks (64 layers) x 32 lanes; lane w
// streams strip-float4 #w (LDG.128 .cs) and abs-accumulates. The 64 MB of
// zero eps rows are written as STG.128 (one per loop iteration, interleaved
// with reads). Warps 1-3 prefetch the epilogue's scattered operands (layer 0,
// noise layer, x_true) into smem during the prologue so the per-block tail is
// latency-free. smem reduce + first-warp decision epilogue; statistically
// dead exact path rewrites after __syncthreads.
// ---------------------------------------------------------------------------
__global__ void __launch_bounds__(128, 16) k_fused(const float* __restrict__ x,
                                                   const float* __restrict__ xtrue,
                                                   float* __restrict__ out) {
    __shared__ float4 sm[4][32];
    __shared__ float2 s_t0[32], s_b0[32];   // layer 0 top/bottom pairs
    __shared__ float2 s_an[32], s_bn[32];   // noise layer pairs
    __shared__ float  s_xt[32];             // x_true window max

    const int t  = threadIdx.x;
    const int w  = t & 31;
    const int ch = t >> 5;                  // 0..3, 64 layers each
    const int wb  = blockIdx.x * 32;        // first window of this block
    const int win = wb + w;
    const int c  = win >> 10;
    const int ho = (win >> 5) & 31;
    const int h0 = 2 * ho;

    // float2 indices of window w's top/bottom segments
    const int r0 = (c * H_DIM + h0) * (W_DIM / 2) + w;
    const int r1 = r0 + (W_DIM / 2);

    const float4* __restrict__ x4 = (const float4*)x;
    const float2* __restrict__ x2 = (const float2*)x;

    // prologue prefetch of epilogue operands (latency hidden by main loop)
    if (ch == 1) {
        s_t0[w] = x2[r0];
        s_b0[w] = x2[r1];
    } else if (ch == 2) {
        s_an[w] = x2[(size_t)(S_TOT - 1) * NPIX2 + r0];
        s_bn[w] = x2[(size_t)(S_TOT - 1) * NPIX2 + r1];
    } else if (ch == 3) {
        const float2* __restrict__ xt2 = (const float2*)xtrue;
        const float2 tt = xt2[r0];
        const float2 tb = xt2[r1];
        s_xt[w] = fmaxf(fmaxf(tt.x, tt.y), fmaxf(tb.x, tb.y));
    }

    // base of the block's 128-float strip, in float4 units
    const int cb  = wb >> 10;
    const int hob = (wb >> 5) & 31;
    const int fb  = (cb * H_DIM + 2 * hob) * (W_DIM / 4);   // float4 index

    // this chunk's 64 symbol layers: s = 1 + ch*64 .. 64 + ch*64
    const float4* __restrict__ p = x4 + (size_t)(1 + ch * 64) * NPIX4 + fb + w;

    float ax = 0.f, ay = 0.f, az = 0.f, aw = 0.f;
    const float4 z4 = make_float4(0.f, 0.f, 0.f, 0.f);

    #pragma unroll 1
    for (int it = 0; it < 16; it++) {
        const int i = it * 4;
        float4 v0 = __ldcs(p + (size_t)(i + 0) * NPIX4);
        float4 v1 = __ldcs(p + (size_t)(i + 1) * NPIX4);
        float4 v2 = __ldcs(p + (size_t)(i + 2) * NPIX4);
        float4 v3 = __ldcs(p + (size_t)(i + 3) * NPIX4);

        ax += fabsf(v0.x); ay += fabsf(v0.y); az += fabsf(v0.z); aw += fabsf(v0.w);
        ax += fabsf(v1.x); ay += fabsf(v1.y); az += fabsf(v1.z); aw += fabsf(v1.w);
        ax += fabsf(v2.x); ay += fabsf(v2.y); az += fabsf(v2.z); aw += fabsf(v2.w);
        ax += fabsf(v3.x); ay += fabsf(v3.y); az += fabsf(v3.z); aw += fabsf(v3.w);

        // one STG.128 of zeros per iteration: 2048 float4 row-chunks total,
        // idx = t + 128*it -> eps row (idx>>3)+1, float4 slot (idx&7)
        const int idx = t + 128 * it;
        const int row = idx >> 3;
        const int xq  = idx & 7;
        __stcs((float4*)(out + (size_t)(1 + row) * NWIN + wb) + xq, z4);
    }

    sm[ch][w] = make_float4(ax, ay, az, aw);
    __syncthreads();

    // ---- first warp: reduce chunks, reassociate pixels->window, decide ----
    if (t < 32) {
        const int lt = w >> 1;          // top-row float4 lane for this window
        const int lb = 16 + lt;         // bottom-row float4 lane

        float4 T = make_float4(0.f, 0.f, 0.f, 0.f);
        float4 B = make_float4(0.f, 0.f, 0.f, 0.f);
        #pragma unroll
        for (int k = 0; k < 4; k++) {
            float4 a = sm[k][lt];
            float4 b = sm[k][lb];
            T.x += a.x; T.y += a.y; T.z += a.z; T.w += a.w;
            B.x += b.x; B.y += b.y; B.z += b.z; B.w += b.w;
        }
        // select this window's pixel pair within the float4
        const bool odd = (w & 1);
        float ET = odd ? T.z : T.x;     // eps_abs of top-left pixel
        float EY = odd ? T.w : T.y;     // top-right
        float EB = odd ? B.z : B.x;     // bottom-left
        float EW = odd ? B.w : B.y;     // bottom-right

        // prefetched layer 0 centers + noise layer values
        const float2 t0 = s_t0[w];
        const float2 b0 = s_b0[w];
        const float2 an = s_an[w];
        const float2 bn = s_bn[w];
        ET += fabsf(an.x); EY += fabsf(an.y); EB += fabsf(bn.x); EW += fabsf(bn.y);

        // interval bounds (K order: [t.x, t.y, b.x, b.y])
        const float lo0 = t0.x - ET, lo1 = t0.y - EY, lo2 = b0.x - EB, lo3 = b0.y - EW;
        const float hi0 = t0.x + ET, hi1 = t0.y + EY, hi2 = b0.x + EB, hi3 = b0.y + EW;

        // argmax of lower bounds, first occurrence wins (matches jnp.argmax)
        int   istar = 0;
        float lbest = lo0;
        if (lo1 > lbest) { lbest = lo1; istar = 1; }
        if (lo2 > lbest) { lbest = lo2; istar = 2; }
        if (lo3 > lbest) { lbest = lo3; istar = 3; }

        const float umax = fmaxf(fmaxf(hi0, hi1), fmaxf(hi2, hi3));

        float uo = -3.0e38f;
        if (istar != 0) uo = fmaxf(uo, hi0);
        if (istar != 1) uo = fmaxf(uo, hi1);
        if (istar != 2) uo = fmaxf(uo, hi2);
        if (istar != 3) uo = fmaxf(uo, hi3);

        const bool exact = (lbest >= uo);

        float center, noise, xmn, xmx;
        if (exact) {
            const float x0g  = (istar == 0) ? t0.x : (istar == 1) ? t0.y
                             : (istar == 2) ? b0.x : b0.y;
            const float epsg = (istar == 0) ? ET   : (istar == 1) ? EY
                             : (istar == 2) ? EB   : EW;
            const float ng   = (istar == 0) ? an.x : (istar == 1) ? an.y
                             : (istar == 2) ? bn.x : bn.y;
            center = x0g;
            noise  = fabsf(ng);
            xmn = center - epsg;          // = l_star
            xmx = center + epsg;          // = u[i_star]

            // rare: rewrite the eps rows with the gathered affine form.
            // Ordered after the zero stores by the __syncthreads above.
            const int dy = istar >> 1;
            const int dx = istar & 1;
            const size_t poff = ((size_t)c * H_DIM + (h0 + dy)) * W_DIM + (2 * w + dx);
            const float* xg = x + NPIX + poff;        // x[1] at chosen pixel
            float* o = out + (size_t)NWIN + win;
            for (int s = 0; s < S_TOT - 2; s++) {
                o[(size_t)s * NWIN] = xg[(size_t)s * NPIX];
            }
        } else {
            center = 0.5f * (lbest + umax);
            noise  = 0.5f * (umax - lbest);
            xmn = center - noise;
            xmx = center + noise;
        }

        // scalar outputs
        out[win]                              = center;   // s = 0
        out[(size_t)(S_TOT - 1) * NWIN + win] = noise;    // s = 257
        out[OFF_XMIN + win]  = xmn;
        out[OFF_XMAX + win]  = xmx;
        out[OFF_XTRUE + win] = s_xt[w];
    }
}

extern "C" void kernel_launch(void* const* d_in, const int* in_sizes, int n_in,
                              void* d_out, int out_size) {
    const float* x  = (const float*)d_in[0];
    const float* xt = (const float*)d_in[1];
    float* out = (float*)d_out;
    (void)in_sizes; (void)n_in; (void)out_size;

    k_fused<<<NWIN / 32, 128>>>(x, xt, out);
}